// round 15
// baseline (speedup 1.0000x reference)
#include <cuda_runtime.h>
#include <cuda_fp16.h>
#include <math.h>
#include <cstdint>

// Problem constants
#define TOK   8192      // B*S
#define CDIM  768
#define FDIM  3072
#define QKVC  2304      // 3*C
#define BB    8
#define SS    1024
#define HH    12
#define DD    64

// ===========================================================================
// Scratch (device globals -- no allocation allowed)
// ===========================================================================
__device__ __half g_wqkv [QKVC * CDIM];   // [N,K] fp16
__device__ __half g_wo   [CDIM * CDIM];
__device__ __half g_wf1  [FDIM * CDIM];
__device__ __half g_wf2  [CDIM * FDIM];
__device__ float  g_qkvb [QKVC];
__device__ __half g_xn  [TOK * CDIM];
__device__ __half g_qkv [TOK * QKVC];
__device__ __half g_ctx [TOK * CDIM];
__device__ float  g_hid [TOK * CDIM];
__device__ __half g_y2  [TOK * CDIM];
__device__ __half g_h1  [TOK * FDIM];

// ===========================================================================
// PTX helpers (base ISA only)
// ===========================================================================
__device__ __forceinline__ uint32_t smem_u32(const void* p) {
    uint32_t a;
    asm("{ .reg .u64 t; cvta.to.shared.u64 t, %1; cvt.u32.u64 %0, t; }"
        : "=r"(a) : "l"(p));
    return a;
}
__device__ __forceinline__ void cp_async16(uint32_t s, const void* g) {
    asm volatile("cp.async.cg.shared.global [%0], [%1], 16;" :: "r"(s), "l"(g));
}
#define CP_COMMIT() asm volatile("cp.async.commit_group;")
#define CP_WAIT0()  asm volatile("cp.async.wait_group 0;")

__device__ __forceinline__ void ldm_x4(uint32_t* r, uint32_t addr) {
    asm volatile("ldmatrix.sync.aligned.m8n8.x4.shared.b16 {%0,%1,%2,%3}, [%4];"
        : "=r"(r[0]), "=r"(r[1]), "=r"(r[2]), "=r"(r[3]) : "r"(addr));
}
__device__ __forceinline__ void ldm_x4t(uint32_t* r, uint32_t addr) {
    asm volatile("ldmatrix.sync.aligned.m8n8.x4.trans.shared.b16 {%0,%1,%2,%3}, [%4];"
        : "=r"(r[0]), "=r"(r[1]), "=r"(r[2]), "=r"(r[3]) : "r"(addr));
}

// D += A @ B  (m16n8k16, fp16 inputs, f32 accum)
__device__ __forceinline__ void mma_f16(float* c, const uint32_t* a, const uint32_t* b) {
    asm volatile(
        "mma.sync.aligned.m16n8k16.row.col.f32.f16.f16.f32 "
        "{%0,%1,%2,%3}, {%4,%5,%6,%7}, {%8,%9}, {%0,%1,%2,%3};"
        : "+f"(c[0]), "+f"(c[1]), "+f"(c[2]), "+f"(c[3])
        : "r"(a[0]), "r"(a[1]), "r"(a[2]), "r"(a[3]), "r"(b[0]), "r"(b[1]));
}

__device__ __forceinline__ uint32_t pack_h2(float x, float y) {
    __half2 t = __floats2half2_rn(x, y);
    return *(uint32_t*)&t;
}

// ===========================================================================
// Fused weight transpose + fp16 convert + bias concat (single launch)
// ===========================================================================
#define WS_BLOCKS 6913   // 4*576 + 2304 + 2304 + 1 (bias)

__global__ __launch_bounds__(256) void wtrans_all(
    const float* __restrict__ qw, const float* __restrict__ kw,
    const float* __restrict__ vw, const float* __restrict__ ow,
    const float* __restrict__ f1, const float* __restrict__ f2,
    const float* __restrict__ qb, const float* __restrict__ kb,
    const float* __restrict__ vb,
    __half* __restrict__ wqkv, __half* __restrict__ wo,
    __half* __restrict__ wf1,  __half* __restrict__ wf2,
    float* __restrict__ qkvb)
{
    int id = blockIdx.x;
    if (id == 6912) {   // bias concat block
        for (int i = threadIdx.x; i < QKVC; i += 256) {
            if (i < CDIM)            qkvb[i] = qb[i];
            else if (i < 2 * CDIM)   qkvb[i] = kb[i - CDIM];
            else                     qkvb[i] = vb[i - 2 * CDIM];
        }
        return;
    }
    const float* W; __half* dst;
    int K, N;
    if (id < 2304) {
        int seg = id / 576, loc = id % 576;
        K = CDIM; N = CDIM;
        if (seg == 0)      { W = qw; dst = wqkv; }
        else if (seg == 1) { W = kw; dst = wqkv + CDIM * CDIM; }
        else if (seg == 2) { W = vw; dst = wqkv + 2 * CDIM * CDIM; }
        else               { W = ow; dst = wo; }
        id = loc;
    } else if (id < 4608) {
        id -= 2304; K = CDIM; N = FDIM; W = f1; dst = wf1;
    } else {
        id -= 4608; K = FDIM; N = CDIM; W = f2; dst = wf2;
    }
    const int nb = N / 32;
    const int n0 = (id % nb) * 32, k0 = (id / nb) * 32;

    __shared__ float t[32][33];
    const int tx = threadIdx.x & 31, ty = threadIdx.x >> 5;
    #pragma unroll
    for (int i = 0; i < 32; i += 8)
        t[ty + i][tx] = W[(size_t)(k0 + ty + i) * N + n0 + tx];
    __syncthreads();
    #pragma unroll
    for (int i = 0; i < 32; i += 8)
        dst[(size_t)(n0 + ty + i) * K + k0 + tx] = __float2half_rn(t[tx][ty + i]);
}

// ===========================================================================
// LayerNorm -> fp16. Warp-per-row (8 rows / 256-thread block).
// ===========================================================================
__global__ __launch_bounds__(256) void ln_f16(
    const float* __restrict__ x, const float* __restrict__ w,
    const float* __restrict__ b, __half* __restrict__ out)
{
    const int row  = blockIdx.x * 8 + (threadIdx.x >> 5);
    const int lane = threadIdx.x & 31;
    const float* xr = x + (size_t)row * CDIM;

    float4 v[6];
    float s = 0.f, s2 = 0.f;
    #pragma unroll
    for (int i = 0; i < 6; i++) {
        v[i] = *(const float4*)(xr + i * 128 + lane * 4);
        s  += v[i].x + v[i].y + v[i].z + v[i].w;
        s2 += v[i].x*v[i].x + v[i].y*v[i].y + v[i].z*v[i].z + v[i].w*v[i].w;
    }
    #pragma unroll
    for (int o = 16; o > 0; o >>= 1) {
        s  += __shfl_xor_sync(0xffffffffu, s,  o);
        s2 += __shfl_xor_sync(0xffffffffu, s2, o);
    }
    const float mu  = s * (1.0f / CDIM);
    const float var = s2 * (1.0f / CDIM) - mu * mu;
    const float inv = rsqrtf(var + 1e-6f);

    size_t ro = (size_t)row * CDIM;
    #pragma unroll
    for (int i = 0; i < 6; i++) {
        int c = i * 128 + lane * 4;
        float4 wv = *(const float4*)(w + c);
        float4 bv = *(const float4*)(b + c);
        float y0 = (v[i].x - mu) * inv * wv.x + bv.x;
        float y1 = (v[i].y - mu) * inv * wv.y + bv.y;
        float y2 = (v[i].z - mu) * inv * wv.z + bv.z;
        float y3 = (v[i].w - mu) * inv * wv.w + bv.w;
        *(uint2*)(out + ro + c) = make_uint2(pack_h2(y0, y1), pack_h2(y2, y3));
    }
}

// ===========================================================================
// fp16 tensor GEMM: C = A @ B^T, 1 MMA per position, BK=64.
// Two-stage double buffer, 1 sync/chunk, 2 CTAs/SM (round-12 proven config).
// EPI 0: +bias -> fp32 ; EPI 1: (+bias)*lam+res -> fp32 ;
// EPI 2: gelu_exact(+bias) -> fp16 ; EPI 3: +bias -> fp16, q cols x 0.125
// ===========================================================================
#define RSB   144                       // bytes per smem row (128 + 16 pad)
#define TILEB (128 * RSB)               // 18432 bytes per tile
#define GEMM_SMEM (4 * TILEB)           // 2 stages x 2 tiles = 73728

template<int EPI>
__global__ __launch_bounds__(256, 2) void mmagemm(
    const __half* __restrict__ A, const __half* __restrict__ B,
    const float* __restrict__ bias,
    int M, int N, int K,
    float* __restrict__ Cf, __half* __restrict__ Ch,
    const float* __restrict__ lam, const float* __restrict__ res)
{
    extern __shared__ char smc[];
    const uint32_t sb = smem_u32(smc);

    const int tid  = threadIdx.x;
    const int wid  = tid >> 5;
    const int lane = tid & 31;
    const int wm   = wid & 1;
    const int wn   = wid >> 1;
    const int m0   = blockIdx.y * 128;
    const int n0   = blockIdx.x * 128;

    auto load_tile = [&](const __half* __restrict__ G, int row0, int k0,
                         uint32_t dst) {
        #pragma unroll
        for (int i = 0; i < 4; i++) {
            int idx = tid + (i << 8);          // 0..1023
            int r   = idx >> 3;
            int cc  = idx & 7;
            cp_async16(dst + r * RSB + cc * 16,
                       G + (size_t)(row0 + r) * K + k0 + cc * 8);
        }
    };
    auto load_chunk = [&](int k0, int p) {
        uint32_t base = sb + (uint32_t)p * (2 * TILEB);
        load_tile(A, m0, k0, base);
        load_tile(B, n0, k0, base + TILEB);
        CP_COMMIT();
    };

    float acc[4][4][4];
    #pragma unroll
    for (int t = 0; t < 4; t++)
        #pragma unroll
        for (int u = 0; u < 4; u++)
            #pragma unroll
            for (int e = 0; e < 4; e++) acc[t][u][e] = 0.f;

    const int nch = K >> 6;   // BK = 64
    load_chunk(0, 0);

    const int aRow = (lane & 7) + ((lane >> 3) & 1) * 8;
    const int aCol = (lane >> 4) * 16;
    const int bRow = (lane & 7) + (lane >> 4) * 8;
    const int bCol = ((lane >> 3) & 1) * 16;

    for (int it = 0; it < nch; ++it) {
        const int p = it & 1;
        CP_WAIT0();
        __syncthreads();
        if (it + 1 < nch) load_chunk((it + 1) << 6, p ^ 1);

        const uint32_t base = sb + (uint32_t)p * (2 * TILEB);
        const uint32_t sA = base;
        const uint32_t sB = base + TILEB;

        #pragma unroll
        for (int ks = 0; ks < 4; ks++) {
            const int kb = ks * 32;
            uint32_t af[4][4];
            #pragma unroll
            for (int t = 0; t < 4; t++) {
                uint32_t ro = (uint32_t)((wm * 64 + t * 16 + aRow) * RSB + kb + aCol);
                ldm_x4(af[t], sA + ro);
            }
            uint32_t bf[2][4];
            #pragma unroll
            for (int u2 = 0; u2 < 2; u2++) {
                uint32_t ro = (uint32_t)((wn * 32 + u2 * 16 + bRow) * RSB + kb + bCol);
                ldm_x4(bf[u2], sB + ro);
            }
            #pragma unroll
            for (int t = 0; t < 4; t++)
                #pragma unroll
                for (int u = 0; u < 4; u++)
                    mma_f16(acc[t][u], af[t], &bf[u >> 1][(u & 1) * 2]);
        }
    }

    #pragma unroll
    for (int t = 0; t < 4; t++) {
        const int rbase = m0 + wm * 64 + t * 16 + (lane >> 2);
        #pragma unroll
        for (int u = 0; u < 4; u++) {
            const int c = n0 + wn * 32 + u * 8 + (lane & 3) * 2;
            #pragma unroll
            for (int half = 0; half < 2; half++) {
                const int r = rbase + half * 8;
                const size_t ro = (size_t)r * N;
                float v0 = acc[t][u][half * 2 + 0] + bias[c];
                float v1 = acc[t][u][half * 2 + 1] + bias[c + 1];
                if (EPI == 1) {
                    v0 = v0 * lam[c]     + res[ro + c];
                    v1 = v1 * lam[c + 1] + res[ro + c + 1];
                    *(float2*)(Cf + ro + c) = make_float2(v0, v1);
                } else if (EPI == 2 || EPI == 3) {
                    if (EPI == 2) {
                        v0 = 0.5f * v0 * (1.0f + erff(v0 * 0.70710678118654752f));
                        v1 = 0.5f * v1 * (1.0f + erff(v1 * 0.70710678118654752f));
                    }
                    if (EPI == 3 && c < CDIM) {   // pre-scale q by 1/sqrt(D)
                        v0 *= 0.125f;
                        v1 *= 0.125f;
                    }
                    *(uint32_t*)(Ch + ro + c) = pack_h2(v0, v1);
                } else {
                    *(float2*)(Cf + ro + c) = make_float2(v0, v1);
                }
            }
        }
    }
}

// ===========================================================================
// Flash attention on tensor cores (fp16, online softmax, fp32 accum).
// BM = 128 q rows/CTA (256 threads, 8 warps x m16), BN = 64 keys/iter.
// Q pre-scaled by 1/sqrt(D) in QKV epilogue. Grid: (S/128, H, B).
// ===========================================================================
#define ARS     144                      // attention smem row stride (bytes)
#define AT_QTILE 18432                   // 128 rows x 144 B
#define AT_TILE  9216                    // 64 rows x 144 B
#define AT_BUF   AT_QTILE                // after Q tile
#define ATT_SMEM (AT_QTILE + 2 * 2 * AT_TILE)  // 55296

__global__ __launch_bounds__(256) void attn_mma(
    const __half* __restrict__ qkv, __half* __restrict__ ctx)
{
    extern __shared__ char smc[];
    const uint32_t sb = smem_u32(smc);
    const int tid  = threadIdx.x;
    const int wid  = tid >> 5;           // 0..7 -> q-row group
    const int lane = tid & 31;
    const int h    = blockIdx.y;
    const int b    = blockIdx.z;
    const int q0   = blockIdx.x * 128;

    // load Q tile: 128 rows x 64 half = 1024 x 16B chunks / 256 thr = 4 each
    for (int i = tid; i < 1024; i += 256) {
        int r = i >> 3, c = i & 7;
        size_t g = (size_t)(b * SS + q0 + r) * QKVC + h * DD + c * 8;
        cp_async16(sb + r * ARS + c * 16, qkv + g);
    }
    CP_COMMIT();

    auto load_kv = [&](int j0, int p) {
        uint32_t base = sb + AT_BUF + (uint32_t)p * (2 * AT_TILE);
        for (int i = tid; i < 512; i += 256) {
            int r = i >> 3, c = i & 7;
            size_t gk = (size_t)(b * SS + j0 + r) * QKVC + CDIM + h * DD + c * 8;
            size_t gv = gk + CDIM;
            cp_async16(base + r * ARS + c * 16,            qkv + gk);
            cp_async16(base + AT_TILE + r * ARS + c * 16,  qkv + gv);
        }
        CP_COMMIT();
    };
    load_kv(0, 0);

    const int aRow = (lane & 7) + ((lane >> 3) & 1) * 8;
    const int aCol = (lane >> 4) * 16;
    const int bRow = (lane & 7) + (lane >> 4) * 8;
    const int bCol = ((lane >> 3) & 1) * 16;
    const int vRow = (lane & 7) + ((lane >> 3) & 1) * 8;
    const int vCol = (lane >> 4) * 16;

    CP_WAIT0();       // Q + kv(0) landed
    __syncthreads();

    uint32_t qf[4][4];
    #pragma unroll
    for (int ks = 0; ks < 4; ks++) {
        uint32_t ro = (uint32_t)((wid * 16 + aRow) * ARS + ks * 32 + aCol);
        ldm_x4(qf[ks], sb + ro);
    }

    float oacc[8][4];
    #pragma unroll
    for (int u = 0; u < 8; u++)
        #pragma unroll
        for (int e = 0; e < 4; e++) oacc[u][e] = 0.f;
    float m0 = -1e30f, m1 = -1e30f, l0 = 0.f, l1 = 0.f;

    const int nt = SS / 64;
    for (int it = 0; it < nt; ++it) {
        const int p = it & 1;
        if (it > 0) {
            CP_WAIT0();
            __syncthreads();
        }
        if (it + 1 < nt) load_kv((it + 1) * 64, p ^ 1);

        const uint32_t base = sb + AT_BUF + (uint32_t)p * (2 * AT_TILE);
        const uint32_t sK = base;
        const uint32_t sV = base + AT_TILE;

        float sacc[8][4];
        #pragma unroll
        for (int u = 0; u < 8; u++)
            #pragma unroll
            for (int e = 0; e < 4; e++) sacc[u][e] = 0.f;

        #pragma unroll
        for (int ks = 0; ks < 4; ks++) {
            const int kb = ks * 32;
            uint32_t kf[4][4];
            #pragma unroll
            for (int g = 0; g < 4; g++) {
                uint32_t ro = (uint32_t)((g * 16 + bRow) * ARS + kb + bCol);
                ldm_x4(kf[g], sK + ro);
            }
            #pragma unroll
            for (int g = 0; g < 4; g++)
                #pragma unroll
                for (int hf = 0; hf < 2; hf++)
                    mma_f16(sacc[g * 2 + hf], qf[ks], &kf[g][hf * 2]);
        }

        // online softmax (scores already scaled by 1/sqrt(D))
        float mx0 = m0, mx1 = m1;
        #pragma unroll
        for (int u = 0; u < 8; u++) {
            mx0 = fmaxf(mx0, fmaxf(sacc[u][0], sacc[u][1]));
            mx1 = fmaxf(mx1, fmaxf(sacc[u][2], sacc[u][3]));
        }
        mx0 = fmaxf(mx0, __shfl_xor_sync(0xffffffffu, mx0, 1));
        mx0 = fmaxf(mx0, __shfl_xor_sync(0xffffffffu, mx0, 2));
        mx1 = fmaxf(mx1, __shfl_xor_sync(0xffffffffu, mx1, 1));
        mx1 = fmaxf(mx1, __shfl_xor_sync(0xffffffffu, mx1, 2));
        float al0 = __expf(m0 - mx0), al1 = __expf(m1 - mx1);
        m0 = mx0; m1 = mx1;
        float sum0 = 0.f, sum1 = 0.f;
        #pragma unroll
        for (int u = 0; u < 8; u++) {
            sacc[u][0] = __expf(sacc[u][0] - m0);
            sacc[u][1] = __expf(sacc[u][1] - m0);
            sacc[u][2] = __expf(sacc[u][2] - m1);
            sacc[u][3] = __expf(sacc[u][3] - m1);
            sum0 += sacc[u][0] + sacc[u][1];
            sum1 += sacc[u][2] + sacc[u][3];
        }
        sum0 += __shfl_xor_sync(0xffffffffu, sum0, 1);
        sum0 += __shfl_xor_sync(0xffffffffu, sum0, 2);
        sum1 += __shfl_xor_sync(0xffffffffu, sum1, 1);
        sum1 += __shfl_xor_sync(0xffffffffu, sum1, 2);
        l0 = l0 * al0 + sum0;
        l1 = l1 * al1 + sum1;
        #pragma unroll
        for (int u = 0; u < 8; u++) {
            oacc[u][0] *= al0; oacc[u][1] *= al0;
            oacc[u][2] *= al1; oacc[u][3] *= al1;
        }

        uint32_t pf[4][4];
        #pragma unroll
        for (int t = 0; t < 4; t++) {
            pf[t][0] = pack_h2(sacc[2*t][0],   sacc[2*t][1]);
            pf[t][1] = pack_h2(sacc[2*t][2],   sacc[2*t][3]);
            pf[t][2] = pack_h2(sacc[2*t+1][0], sacc[2*t+1][1]);
            pf[t][3] = pack_h2(sacc[2*t+1][2], sacc[2*t+1][3]);
        }

        #pragma unroll
        for (int t = 0; t < 4; t++) {
            uint32_t vf[4][4];
            #pragma unroll
            for (int g = 0; g < 4; g++) {
                uint32_t ro = (uint32_t)((t * 16 + vRow) * ARS + g * 32 + vCol);
                ldm_x4t(vf[g], sV + ro);
            }
            #pragma unroll
            for (int g = 0; g < 4; g++)
                #pragma unroll
                for (int hf = 0; hf < 2; hf++)
                    mma_f16(oacc[g * 2 + hf], pf[t], &vf[g][hf * 2]);
        }
    }

    float inv0 = 1.0f / l0, inv1 = 1.0f / l1;
    const int r  = lane >> 2;
    const int cc = (lane & 3) * 2;
    #pragma unroll
    for (int u = 0; u < 8; u++) {
        int col = h * DD + u * 8 + cc;
        size_t o0 = (size_t)(b * SS + q0 + wid * 16 + r)     * CDIM + col;
        size_t o1 = (size_t)(b * SS + q0 + wid * 16 + r + 8) * CDIM + col;
        *(uint32_t*)(ctx + o0) = pack_h2(oacc[u][0] * inv0, oacc[u][1] * inv0);
        *(uint32_t*)(ctx + o1) = pack_h2(oacc[u][2] * inv1, oacc[u][3] * inv1);
    }
}

// ===========================================================================
// Launch
// ===========================================================================
extern "C" void kernel_launch(void* const* d_in, const int* in_sizes, int n_in,
                              void* d_out, int out_size)
{
    const float* hs    = (const float*)d_in[0];
    const float* ln1_w = (const float*)d_in[1];
    const float* ln1_b = (const float*)d_in[2];
    const float* q_w   = (const float*)d_in[3];
    const float* q_b   = (const float*)d_in[4];
    const float* k_w   = (const float*)d_in[5];
    const float* k_b   = (const float*)d_in[6];
    const float* v_w   = (const float*)d_in[7];
    const float* v_b   = (const float*)d_in[8];
    const float* o_w   = (const float*)d_in[9];
    const float* o_b   = (const float*)d_in[10];
    const float* lam1  = (const float*)d_in[11];
    const float* ln2_w = (const float*)d_in[12];
    const float* ln2_b = (const float*)d_in[13];
    const float* fc1_w = (const float*)d_in[14];
    const float* fc1_b = (const float*)d_in[15];
    const float* fc2_w = (const float*)d_in[16];
    const float* fc2_b = (const float*)d_in[17];
    const float* lam2  = (const float*)d_in[18];
    float* out = (float*)d_out;

    __half *wqkv, *wo, *wf1, *wf2, *xn, *qkv, *ctx, *y2, *h1;
    float *qkvb, *hid;
    cudaGetSymbolAddress((void**)&wqkv, g_wqkv);
    cudaGetSymbolAddress((void**)&wo,   g_wo);
    cudaGetSymbolAddress((void**)&wf1,  g_wf1);
    cudaGetSymbolAddress((void**)&wf2,  g_wf2);
    cudaGetSymbolAddress((void**)&qkvb, g_qkvb);
    cudaGetSymbolAddress((void**)&xn,   g_xn);
    cudaGetSymbolAddress((void**)&qkv,  g_qkv);
    cudaGetSymbolAddress((void**)&ctx,  g_ctx);
    cudaGetSymbolAddress((void**)&hid,  g_hid);
    cudaGetSymbolAddress((void**)&y2,   g_y2);
    cudaGetSymbolAddress((void**)&h1,   g_h1);

    // 1) weight prep + bias concat (single launch)
    wtrans_all<<<WS_BLOCKS, 256>>>(q_w, k_w, v_w, o_w, fc1_w, fc2_w,
                                   q_b, k_b, v_b,
                                   wqkv, wo, wf1, wf2, qkvb);

    cudaFuncSetAttribute(mmagemm<1>, cudaFuncAttributeMaxDynamicSharedMemorySize, GEMM_SMEM);
    cudaFuncSetAttribute(mmagemm<2>, cudaFuncAttributeMaxDynamicSharedMemorySize, GEMM_SMEM);
    cudaFuncSetAttribute(mmagemm<3>, cudaFuncAttributeMaxDynamicSharedMemorySize, GEMM_SMEM);
    cudaFuncSetAttribute(attn_mma,   cudaFuncAttributeMaxDynamicSharedMemorySize, ATT_SMEM);

    // 2) LN1 -> fp16
    ln_f16<<<TOK / 8, 256>>>(hs, ln1_w, ln1_b, xn);

    // 3) fused QKV -> fp16 (q columns pre-scaled by 1/sqrt(D))
    mmagemm<3><<<dim3(QKVC / 128, TOK / 128), 256, GEMM_SMEM>>>(
        xn, wqkv, qkvb, TOK, QKVC, CDIM, nullptr, qkv, nullptr, nullptr);

    // 4) attention -> ctx fp16 (BM=128)
    attn_mma<<<dim3(SS / 128, HH, BB), 256, ATT_SMEM>>>(qkv, ctx);

    // 5) O projection + lam1*. + shortcut -> hid fp32
    mmagemm<1><<<dim3(CDIM / 128, TOK / 128), 256, GEMM_SMEM>>>(
        ctx, wo, o_b, TOK, CDIM, CDIM, hid, nullptr, lam1, hs);

    // 6) LN2 -> fp16
    ln_f16<<<TOK / 8, 256>>>(hid, ln2_w, ln2_b, y2);

    // 7) FC1 + exact GELU -> fp16
    mmagemm<2><<<dim3(FDIM / 128, TOK / 128), 256, GEMM_SMEM>>>(
        y2, wf1, fc1_b, TOK, FDIM, CDIM, nullptr, h1, nullptr, nullptr);

    // 8) FC2 + lam2*. + hid -> out fp32
    mmagemm<1><<<dim3(CDIM / 128, TOK / 128), 256, GEMM_SMEM>>>(
        h1, wf2, fc2_b, TOK, CDIM, FDIM, out, nullptr, lam2, hid);
}

// round 16
// speedup vs baseline: 1.0257x; 1.0257x over previous
#include <cuda_runtime.h>
#include <cuda_fp16.h>
#include <math.h>
#include <cstdint>

// Problem constants
#define TOK   8192      // B*S
#define CDIM  768
#define FDIM  3072
#define QKVC  2304      // 3*C
#define BB    8
#define SS    1024
#define HH    12
#define DD    64

// ===========================================================================
// Scratch (device globals -- no allocation allowed)
// ===========================================================================
__device__ __half g_wqkv [QKVC * CDIM];   // [N,K] fp16
__device__ __half g_wo   [CDIM * CDIM];
__device__ __half g_wf1  [FDIM * CDIM];
__device__ __half g_wf2  [CDIM * FDIM];
__device__ float  g_qkvb [QKVC];
__device__ __half g_xn  [TOK * CDIM];
__device__ __half g_qkv [TOK * QKVC];
__device__ __half g_ctx [TOK * CDIM];
__device__ float  g_hid [TOK * CDIM];
__device__ __half g_y2  [TOK * CDIM];
__device__ __half g_h1  [TOK * FDIM];

// ===========================================================================
// PTX helpers (base ISA only)
// ===========================================================================
__device__ __forceinline__ uint32_t smem_u32(const void* p) {
    uint32_t a;
    asm("{ .reg .u64 t; cvta.to.shared.u64 t, %1; cvt.u32.u64 %0, t; }"
        : "=r"(a) : "l"(p));
    return a;
}
__device__ __forceinline__ void cp_async16(uint32_t s, const void* g) {
    asm volatile("cp.async.cg.shared.global [%0], [%1], 16;" :: "r"(s), "l"(g));
}
#define CP_COMMIT() asm volatile("cp.async.commit_group;")
#define CP_WAIT0()  asm volatile("cp.async.wait_group 0;")

__device__ __forceinline__ void ldm_x4(uint32_t* r, uint32_t addr) {
    asm volatile("ldmatrix.sync.aligned.m8n8.x4.shared.b16 {%0,%1,%2,%3}, [%4];"
        : "=r"(r[0]), "=r"(r[1]), "=r"(r[2]), "=r"(r[3]) : "r"(addr));
}
__device__ __forceinline__ void ldm_x4t(uint32_t* r, uint32_t addr) {
    asm volatile("ldmatrix.sync.aligned.m8n8.x4.trans.shared.b16 {%0,%1,%2,%3}, [%4];"
        : "=r"(r[0]), "=r"(r[1]), "=r"(r[2]), "=r"(r[3]) : "r"(addr));
}

// D += A @ B  (m16n8k16, fp16 inputs, f32 accum)
__device__ __forceinline__ void mma_f16(float* c, const uint32_t* a, const uint32_t* b) {
    asm volatile(
        "mma.sync.aligned.m16n8k16.row.col.f32.f16.f16.f32 "
        "{%0,%1,%2,%3}, {%4,%5,%6,%7}, {%8,%9}, {%0,%1,%2,%3};"
        : "+f"(c[0]), "+f"(c[1]), "+f"(c[2]), "+f"(c[3])
        : "r"(a[0]), "r"(a[1]), "r"(a[2]), "r"(a[3]), "r"(b[0]), "r"(b[1]));
}

__device__ __forceinline__ uint32_t pack_h2(float x, float y) {
    __half2 t = __floats2half2_rn(x, y);
    return *(uint32_t*)&t;
}

// ===========================================================================
// Fused weight transpose + fp16 convert + bias concat (single launch)
// ===========================================================================
#define WS_BLOCKS 6913   // 4*576 + 2304 + 2304 + 1 (bias)

__global__ __launch_bounds__(256) void wtrans_all(
    const float* __restrict__ qw, const float* __restrict__ kw,
    const float* __restrict__ vw, const float* __restrict__ ow,
    const float* __restrict__ f1, const float* __restrict__ f2,
    const float* __restrict__ qb, const float* __restrict__ kb,
    const float* __restrict__ vb,
    __half* __restrict__ wqkv, __half* __restrict__ wo,
    __half* __restrict__ wf1,  __half* __restrict__ wf2,
    float* __restrict__ qkvb)
{
    int id = blockIdx.x;
    if (id == 6912) {   // bias concat block
        for (int i = threadIdx.x; i < QKVC; i += 256) {
            if (i < CDIM)            qkvb[i] = qb[i];
            else if (i < 2 * CDIM)   qkvb[i] = kb[i - CDIM];
            else                     qkvb[i] = vb[i - 2 * CDIM];
        }
        return;
    }
    const float* W; __half* dst;
    int K, N;
    if (id < 2304) {
        int seg = id / 576, loc = id % 576;
        K = CDIM; N = CDIM;
        if (seg == 0)      { W = qw; dst = wqkv; }
        else if (seg == 1) { W = kw; dst = wqkv + CDIM * CDIM; }
        else if (seg == 2) { W = vw; dst = wqkv + 2 * CDIM * CDIM; }
        else               { W = ow; dst = wo; }
        id = loc;
    } else if (id < 4608) {
        id -= 2304; K = CDIM; N = FDIM; W = f1; dst = wf1;
    } else {
        id -= 4608; K = FDIM; N = CDIM; W = f2; dst = wf2;
    }
    const int nb = N / 32;
    const int n0 = (id % nb) * 32, k0 = (id / nb) * 32;

    __shared__ float t[32][33];
    const int tx = threadIdx.x & 31, ty = threadIdx.x >> 5;
    #pragma unroll
    for (int i = 0; i < 32; i += 8)
        t[ty + i][tx] = W[(size_t)(k0 + ty + i) * N + n0 + tx];
    __syncthreads();
    #pragma unroll
    for (int i = 0; i < 32; i += 8)
        dst[(size_t)(n0 + ty + i) * K + k0 + tx] = __float2half_rn(t[tx][ty + i]);
}

// ===========================================================================
// LayerNorm -> fp16. Warp-per-row (8 rows / 256-thread block).
// ===========================================================================
__global__ __launch_bounds__(256) void ln_f16(
    const float* __restrict__ x, const float* __restrict__ w,
    const float* __restrict__ b, __half* __restrict__ out)
{
    const int row  = blockIdx.x * 8 + (threadIdx.x >> 5);
    const int lane = threadIdx.x & 31;
    const float* xr = x + (size_t)row * CDIM;

    float4 v[6];
    float s = 0.f, s2 = 0.f;
    #pragma unroll
    for (int i = 0; i < 6; i++) {
        v[i] = *(const float4*)(xr + i * 128 + lane * 4);
        s  += v[i].x + v[i].y + v[i].z + v[i].w;
        s2 += v[i].x*v[i].x + v[i].y*v[i].y + v[i].z*v[i].z + v[i].w*v[i].w;
    }
    #pragma unroll
    for (int o = 16; o > 0; o >>= 1) {
        s  += __shfl_xor_sync(0xffffffffu, s,  o);
        s2 += __shfl_xor_sync(0xffffffffu, s2, o);
    }
    const float mu  = s * (1.0f / CDIM);
    const float var = s2 * (1.0f / CDIM) - mu * mu;
    const float inv = rsqrtf(var + 1e-6f);

    size_t ro = (size_t)row * CDIM;
    #pragma unroll
    for (int i = 0; i < 6; i++) {
        int c = i * 128 + lane * 4;
        float4 wv = *(const float4*)(w + c);
        float4 bv = *(const float4*)(b + c);
        float y0 = (v[i].x - mu) * inv * wv.x + bv.x;
        float y1 = (v[i].y - mu) * inv * wv.y + bv.y;
        float y2 = (v[i].z - mu) * inv * wv.z + bv.z;
        float y3 = (v[i].w - mu) * inv * wv.w + bv.w;
        *(uint2*)(out + ro + c) = make_uint2(pack_h2(y0, y1), pack_h2(y2, y3));
    }
}

// ===========================================================================
// fp16 tensor GEMM: C = A @ B^T, 1 MMA per position, BK=64.
// Two-stage double buffer, 1 sync/chunk, 2 CTAs/SM (round-12 proven config).
// EPI 0: +bias -> fp32 ; EPI 1: (+bias)*lam+res -> fp32 ;
// EPI 2: gelu_exact(+bias) -> fp16 ;
// EPI 3: +bias -> fp16, q cols x (0.125*log2e) for base-2 softmax
// ===========================================================================
#define RSB   144                       // bytes per smem row (128 + 16 pad)
#define TILEB (128 * RSB)               // 18432 bytes per tile
#define GEMM_SMEM (4 * TILEB)           // 2 stages x 2 tiles = 73728

#define QSCALE 0.180336880026217f       // 0.125 * log2(e)

template<int EPI>
__global__ __launch_bounds__(256, 2) void mmagemm(
    const __half* __restrict__ A, const __half* __restrict__ B,
    const float* __restrict__ bias,
    int M, int N, int K,
    float* __restrict__ Cf, __half* __restrict__ Ch,
    const float* __restrict__ lam, const float* __restrict__ res)
{
    extern __shared__ char smc[];
    const uint32_t sb = smem_u32(smc);

    const int tid  = threadIdx.x;
    const int wid  = tid >> 5;
    const int lane = tid & 31;
    const int wm   = wid & 1;
    const int wn   = wid >> 1;
    const int m0   = blockIdx.y * 128;
    const int n0   = blockIdx.x * 128;

    auto load_tile = [&](const __half* __restrict__ G, int row0, int k0,
                         uint32_t dst) {
        #pragma unroll
        for (int i = 0; i < 4; i++) {
            int idx = tid + (i << 8);          // 0..1023
            int r   = idx >> 3;
            int cc  = idx & 7;
            cp_async16(dst + r * RSB + cc * 16,
                       G + (size_t)(row0 + r) * K + k0 + cc * 8);
        }
    };
    auto load_chunk = [&](int k0, int p) {
        uint32_t base = sb + (uint32_t)p * (2 * TILEB);
        load_tile(A, m0, k0, base);
        load_tile(B, n0, k0, base + TILEB);
        CP_COMMIT();
    };

    float acc[4][4][4];
    #pragma unroll
    for (int t = 0; t < 4; t++)
        #pragma unroll
        for (int u = 0; u < 4; u++)
            #pragma unroll
            for (int e = 0; e < 4; e++) acc[t][u][e] = 0.f;

    const int nch = K >> 6;   // BK = 64
    load_chunk(0, 0);

    const int aRow = (lane & 7) + ((lane >> 3) & 1) * 8;
    const int aCol = (lane >> 4) * 16;
    const int bRow = (lane & 7) + (lane >> 4) * 8;
    const int bCol = ((lane >> 3) & 1) * 16;

    for (int it = 0; it < nch; ++it) {
        const int p = it & 1;
        CP_WAIT0();
        __syncthreads();
        if (it + 1 < nch) load_chunk((it + 1) << 6, p ^ 1);

        const uint32_t base = sb + (uint32_t)p * (2 * TILEB);
        const uint32_t sA = base;
        const uint32_t sB = base + TILEB;

        #pragma unroll
        for (int ks = 0; ks < 4; ks++) {
            const int kb = ks * 32;
            uint32_t af[4][4];
            #pragma unroll
            for (int t = 0; t < 4; t++) {
                uint32_t ro = (uint32_t)((wm * 64 + t * 16 + aRow) * RSB + kb + aCol);
                ldm_x4(af[t], sA + ro);
            }
            uint32_t bf[2][4];
            #pragma unroll
            for (int u2 = 0; u2 < 2; u2++) {
                uint32_t ro = (uint32_t)((wn * 32 + u2 * 16 + bRow) * RSB + kb + bCol);
                ldm_x4(bf[u2], sB + ro);
            }
            #pragma unroll
            for (int t = 0; t < 4; t++)
                #pragma unroll
                for (int u = 0; u < 4; u++)
                    mma_f16(acc[t][u], af[t], &bf[u >> 1][(u & 1) * 2]);
        }
    }

    #pragma unroll
    for (int t = 0; t < 4; t++) {
        const int rbase = m0 + wm * 64 + t * 16 + (lane >> 2);
        #pragma unroll
        for (int u = 0; u < 4; u++) {
            const int c = n0 + wn * 32 + u * 8 + (lane & 3) * 2;
            #pragma unroll
            for (int half = 0; half < 2; half++) {
                const int r = rbase + half * 8;
                const size_t ro = (size_t)r * N;
                float v0 = acc[t][u][half * 2 + 0] + bias[c];
                float v1 = acc[t][u][half * 2 + 1] + bias[c + 1];
                if (EPI == 1) {
                    v0 = v0 * lam[c]     + res[ro + c];
                    v1 = v1 * lam[c + 1] + res[ro + c + 1];
                    *(float2*)(Cf + ro + c) = make_float2(v0, v1);
                } else if (EPI == 2 || EPI == 3) {
                    if (EPI == 2) {
                        v0 = 0.5f * v0 * (1.0f + erff(v0 * 0.70710678118654752f));
                        v1 = 0.5f * v1 * (1.0f + erff(v1 * 0.70710678118654752f));
                    }
                    if (EPI == 3 && c < CDIM) {   // q pre-scale: 1/sqrt(D) * log2e
                        v0 *= QSCALE;
                        v1 *= QSCALE;
                    }
                    *(uint32_t*)(Ch + ro + c) = pack_h2(v0, v1);
                } else {
                    *(float2*)(Cf + ro + c) = make_float2(v0, v1);
                }
            }
        }
    }
}

// ===========================================================================
// Flash attention on tensor cores (fp16, base-2 online softmax, fp32 accum).
// BM = 64, 128 threads (4 warps x m16). Scores arrive in log2 units (q
// pre-scaled by 0.125*log2e), so probabilities use bare exp2f.
// Grid: (S/64, H, B).
// ===========================================================================
#define ARS     144                      // attention smem row stride (bytes)
#define AT_TILE 9216                     // 64 rows x 144 B
#define AT_BUF  AT_TILE                  // after Q tile
#define ATT_SMEM (AT_TILE + 2 * 2 * AT_TILE)  // 46080

__global__ __launch_bounds__(128) void attn_mma(
    const __half* __restrict__ qkv, __half* __restrict__ ctx)
{
    extern __shared__ char smc[];
    const uint32_t sb = smem_u32(smc);
    const int tid  = threadIdx.x;
    const int wid  = tid >> 5;
    const int lane = tid & 31;
    const int h    = blockIdx.y;
    const int b    = blockIdx.z;
    const int q0   = blockIdx.x * 64;

    for (int i = tid; i < 512; i += 128) {
        int r = i >> 3, c = i & 7;
        size_t g = (size_t)(b * SS + q0 + r) * QKVC + h * DD + c * 8;
        cp_async16(sb + r * ARS + c * 16, qkv + g);
    }
    CP_COMMIT();

    auto load_kv = [&](int j0, int p) {
        uint32_t base = sb + AT_BUF + (uint32_t)p * (2 * AT_TILE);
        for (int i = tid; i < 512; i += 128) {
            int r = i >> 3, c = i & 7;
            size_t gk = (size_t)(b * SS + j0 + r) * QKVC + CDIM + h * DD + c * 8;
            size_t gv = gk + CDIM;
            cp_async16(base + r * ARS + c * 16,            qkv + gk);
            cp_async16(base + AT_TILE + r * ARS + c * 16,  qkv + gv);
        }
        CP_COMMIT();
    };
    load_kv(0, 0);

    const int aRow = (lane & 7) + ((lane >> 3) & 1) * 8;
    const int aCol = (lane >> 4) * 16;
    const int bRow = (lane & 7) + (lane >> 4) * 8;
    const int bCol = ((lane >> 3) & 1) * 16;
    const int vRow = (lane & 7) + ((lane >> 3) & 1) * 8;
    const int vCol = (lane >> 4) * 16;

    CP_WAIT0();       // Q + kv(0) landed
    __syncthreads();

    uint32_t qf[4][4];
    #pragma unroll
    for (int ks = 0; ks < 4; ks++) {
        uint32_t ro = (uint32_t)((wid * 16 + aRow) * ARS + ks * 32 + aCol);
        ldm_x4(qf[ks], sb + ro);
    }

    float oacc[8][4];
    #pragma unroll
    for (int u = 0; u < 8; u++)
        #pragma unroll
        for (int e = 0; e < 4; e++) oacc[u][e] = 0.f;
    float m0 = -1e30f, m1 = -1e30f, l0 = 0.f, l1 = 0.f;

    const int nt = SS / 64;
    for (int it = 0; it < nt; ++it) {
        const int p = it & 1;
        if (it > 0) {
            CP_WAIT0();
            __syncthreads();
        }
        if (it + 1 < nt) load_kv((it + 1) * 64, p ^ 1);

        const uint32_t base = sb + AT_BUF + (uint32_t)p * (2 * AT_TILE);
        const uint32_t sK = base;
        const uint32_t sV = base + AT_TILE;

        float sacc[8][4];
        #pragma unroll
        for (int u = 0; u < 8; u++)
            #pragma unroll
            for (int e = 0; e < 4; e++) sacc[u][e] = 0.f;

        #pragma unroll
        for (int ks = 0; ks < 4; ks++) {
            const int kb = ks * 32;
            uint32_t kf[4][4];
            #pragma unroll
            for (int g = 0; g < 4; g++) {
                uint32_t ro = (uint32_t)((g * 16 + bRow) * ARS + kb + bCol);
                ldm_x4(kf[g], sK + ro);
            }
            #pragma unroll
            for (int g = 0; g < 4; g++)
                #pragma unroll
                for (int hf = 0; hf < 2; hf++)
                    mma_f16(sacc[g * 2 + hf], qf[ks], &kf[g][hf * 2]);
        }

        // base-2 online softmax (scores already in log2 units)
        float mx0 = m0, mx1 = m1;
        #pragma unroll
        for (int u = 0; u < 8; u++) {
            mx0 = fmaxf(mx0, fmaxf(sacc[u][0], sacc[u][1]));
            mx1 = fmaxf(mx1, fmaxf(sacc[u][2], sacc[u][3]));
        }
        mx0 = fmaxf(mx0, __shfl_xor_sync(0xffffffffu, mx0, 1));
        mx0 = fmaxf(mx0, __shfl_xor_sync(0xffffffffu, mx0, 2));
        mx1 = fmaxf(mx1, __shfl_xor_sync(0xffffffffu, mx1, 1));
        mx1 = fmaxf(mx1, __shfl_xor_sync(0xffffffffu, mx1, 2));
        float al0 = exp2f(m0 - mx0), al1 = exp2f(m1 - mx1);
        m0 = mx0; m1 = mx1;
        float sum0 = 0.f, sum1 = 0.f;
        #pragma unroll
        for (int u = 0; u < 8; u++) {
            sacc[u][0] = exp2f(sacc[u][0] - m0);
            sacc[u][1] = exp2f(sacc[u][1] - m0);
            sacc[u][2] = exp2f(sacc[u][2] - m1);
            sacc[u][3] = exp2f(sacc[u][3] - m1);
            sum0 += sacc[u][0] + sacc[u][1];
            sum1 += sacc[u][2] + sacc[u][3];
        }
        sum0 += __shfl_xor_sync(0xffffffffu, sum0, 1);
        sum0 += __shfl_xor_sync(0xffffffffu, sum0, 2);
        sum1 += __shfl_xor_sync(0xffffffffu, sum1, 1);
        sum1 += __shfl_xor_sync(0xffffffffu, sum1, 2);
        l0 = l0 * al0 + sum0;
        l1 = l1 * al1 + sum1;
        #pragma unroll
        for (int u = 0; u < 8; u++) {
            oacc[u][0] *= al0; oacc[u][1] *= al0;
            oacc[u][2] *= al1; oacc[u][3] *= al1;
        }

        uint32_t pf[4][4];
        #pragma unroll
        for (int t = 0; t < 4; t++) {
            pf[t][0] = pack_h2(sacc[2*t][0],   sacc[2*t][1]);
            pf[t][1] = pack_h2(sacc[2*t][2],   sacc[2*t][3]);
            pf[t][2] = pack_h2(sacc[2*t+1][0], sacc[2*t+1][1]);
            pf[t][3] = pack_h2(sacc[2*t+1][2], sacc[2*t+1][3]);
        }

        #pragma unroll
        for (int t = 0; t < 4; t++) {
            uint32_t vf[4][4];
            #pragma unroll
            for (int g = 0; g < 4; g++) {
                uint32_t ro = (uint32_t)((t * 16 + vRow) * ARS + g * 32 + vCol);
                ldm_x4t(vf[g], sV + ro);
            }
            #pragma unroll
            for (int g = 0; g < 4; g++)
                #pragma unroll
                for (int hf = 0; hf < 2; hf++)
                    mma_f16(oacc[g * 2 + hf], pf[t], &vf[g][hf * 2]);
        }
    }

    float inv0 = 1.0f / l0, inv1 = 1.0f / l1;
    const int r  = lane >> 2;
    const int cc = (lane & 3) * 2;
    #pragma unroll
    for (int u = 0; u < 8; u++) {
        int col = h * DD + u * 8 + cc;
        size_t o0 = (size_t)(b * SS + q0 + wid * 16 + r)     * CDIM + col;
        size_t o1 = (size_t)(b * SS + q0 + wid * 16 + r + 8) * CDIM + col;
        *(uint32_t*)(ctx + o0) = pack_h2(oacc[u][0] * inv0, oacc[u][1] * inv0);
        *(uint32_t*)(ctx + o1) = pack_h2(oacc[u][2] * inv1, oacc[u][3] * inv1);
    }
}

// ===========================================================================
// Launch
// ===========================================================================
extern "C" void kernel_launch(void* const* d_in, const int* in_sizes, int n_in,
                              void* d_out, int out_size)
{
    const float* hs    = (const float*)d_in[0];
    const float* ln1_w = (const float*)d_in[1];
    const float* ln1_b = (const float*)d_in[2];
    const float* q_w   = (const float*)d_in[3];
    const float* q_b   = (const float*)d_in[4];
    const float* k_w   = (const float*)d_in[5];
    const float* k_b   = (const float*)d_in[6];
    const float* v_w   = (const float*)d_in[7];
    const float* v_b   = (const float*)d_in[8];
    const float* o_w   = (const float*)d_in[9];
    const float* o_b   = (const float*)d_in[10];
    const float* lam1  = (const float*)d_in[11];
    const float* ln2_w = (const float*)d_in[12];
    const float* ln2_b = (const float*)d_in[13];
    const float* fc1_w = (const float*)d_in[14];
    const float* fc1_b = (const float*)d_in[15];
    const float* fc2_w = (const float*)d_in[16];
    const float* fc2_b = (const float*)d_in[17];
    const float* lam2  = (const float*)d_in[18];
    float* out = (float*)d_out;

    __half *wqkv, *wo, *wf1, *wf2, *xn, *qkv, *ctx, *y2, *h1;
    float *qkvb, *hid;
    cudaGetSymbolAddress((void**)&wqkv, g_wqkv);
    cudaGetSymbolAddress((void**)&wo,   g_wo);
    cudaGetSymbolAddress((void**)&wf1,  g_wf1);
    cudaGetSymbolAddress((void**)&wf2,  g_wf2);
    cudaGetSymbolAddress((void**)&qkvb, g_qkvb);
    cudaGetSymbolAddress((void**)&xn,   g_xn);
    cudaGetSymbolAddress((void**)&qkv,  g_qkv);
    cudaGetSymbolAddress((void**)&ctx,  g_ctx);
    cudaGetSymbolAddress((void**)&hid,  g_hid);
    cudaGetSymbolAddress((void**)&y2,   g_y2);
    cudaGetSymbolAddress((void**)&h1,   g_h1);

    // 1) weight prep + bias concat (single launch)
    wtrans_all<<<WS_BLOCKS, 256>>>(q_w, k_w, v_w, o_w, fc1_w, fc2_w,
                                   q_b, k_b, v_b,
                                   wqkv, wo, wf1, wf2, qkvb);

    cudaFuncSetAttribute(mmagemm<1>, cudaFuncAttributeMaxDynamicSharedMemorySize, GEMM_SMEM);
    cudaFuncSetAttribute(mmagemm<2>, cudaFuncAttributeMaxDynamicSharedMemorySize, GEMM_SMEM);
    cudaFuncSetAttribute(mmagemm<3>, cudaFuncAttributeMaxDynamicSharedMemorySize, GEMM_SMEM);
    cudaFuncSetAttribute(attn_mma,   cudaFuncAttributeMaxDynamicSharedMemorySize, ATT_SMEM);

    // 2) LN1 -> fp16
    ln_f16<<<TOK / 8, 256>>>(hs, ln1_w, ln1_b, xn);

    // 3) fused QKV -> fp16 (q columns pre-scaled by 0.125*log2e)
    mmagemm<3><<<dim3(QKVC / 128, TOK / 128), 256, GEMM_SMEM>>>(
        xn, wqkv, qkvb, TOK, QKVC, CDIM, nullptr, qkv, nullptr, nullptr);

    // 4) attention -> ctx fp16 (BM=64, base-2 softmax)
    attn_mma<<<dim3(SS / 64, HH, BB), 128, ATT_SMEM>>>(qkv, ctx);

    // 5) O projection + lam1*. + shortcut -> hid fp32
    mmagemm<1><<<dim3(CDIM / 128, TOK / 128), 256, GEMM_SMEM>>>(
        ctx, wo, o_b, TOK, CDIM, CDIM, hid, nullptr, lam1, hs);

    // 6) LN2 -> fp16
    ln_f16<<<TOK / 8, 256>>>(hid, ln2_w, ln2_b, y2);

    // 7) FC1 + exact GELU -> fp16
    mmagemm<2><<<dim3(FDIM / 128, TOK / 128), 256, GEMM_SMEM>>>(
        y2, wf1, fc1_b, TOK, FDIM, CDIM, nullptr, h1, nullptr, nullptr);

    // 8) FC2 + lam2*. + hid -> out fp32
    mmagemm<1><<<dim3(CDIM / 128, TOK / 128), 256, GEMM_SMEM>>>(
        h1, wf2, fc2_b, TOK, CDIM, FDIM, out, nullptr, lam2, hid);
}